// round 1
// baseline (speedup 1.0000x reference)
#include <cuda_runtime.h>

// QKVAttention: out[n,c,t] = sum_s softmax_s( (q.k)/8 + mask )[t,s] * v[c,s]
//   q = qkv[n, 0:64, :]          (per-head channels x T)
//   k = [enc_k | qkv[n,64:128,:]]  length L = 77 + 2048 = 2125
//   v = [enc_v | qkv[n,128:192,:]]
// fp32 flash-attention baseline: block = one (n, 64-query tile), s-chunks of 64.

#define NB    32
#define CHD   64
#define TLEN  2048
#define SLEN  77
#define LLEN  (SLEN + TLEN)            // 2125
#define BT    64
#define BS    64
#define NCHUNK ((LLEN + BS - 1) / BS)  // 34
#define PAD   68                       // padded stride for transposed tiles

// smem (floats): qs[64][64] | ks[64][64] | vs[64][PAD] | ws[64][PAD] | alpha[64] | l[64]
#define SMEM_FLOATS (64*64 + 64*64 + 64*PAD + 64*PAD + 64 + 64)   // 17024

__global__ void __launch_bounds__(256, 2)
attn_fa32_kernel(const float* __restrict__ qkv,
                 const float* __restrict__ enc,
                 const float* __restrict__ mask,
                 float* __restrict__ out)
{
    extern __shared__ float sm[];
    float* qs   = sm;                    // [c][t]  stride 64
    float* ks   = sm + 64*64;            // [c][s]  stride 64
    float* vs   = sm + 2*64*64;          // [s][c]  stride PAD (transposed)
    float* ws   = vs + 64*PAD;           // [s][t]  stride PAD (P transposed)
    float* al_s = ws + 64*PAD;           // [64] per-row rescale factor
    float* l_s  = al_s + 64;             // [64] final denominators

    const int tid = threadIdx.x;
    const int ty  = tid >> 4;            // 0..15
    const int tx  = tid & 15;            // 0..15
    const int n   = blockIdx.y;
    const int t0  = blockIdx.x * BT;

    const float* qb  = qkv + (size_t)n * (3 * CHD * TLEN);  // q  [c][t]
    const float* kb  = qb + CHD * TLEN;                      // self-k
    const float* vb  = qb + 2 * CHD * TLEN;                  // self-v
    const float* ekb = enc + (size_t)n * (2 * CHD * SLEN);   // enc-k [c][s]
    const float* evb = ekb + CHD * SLEN;                     // enc-v

    // Load Q tile, folding both scale factors: logits = (q/8).k + mask
    for (int idx = tid; idx < CHD * BT; idx += 256) {
        int c = idx >> 6, t = idx & 63;
        qs[idx] = qb[c * TLEN + t0 + t] * 0.125f;
    }

    // Output accumulators: rows c = ty*4+i, cols t = tx*4+j
    float acc[4][4];
    float m_row[4], l_row[4];   // online-softmax state for rows t = ty*4+i (QK mapping)
#pragma unroll
    for (int i = 0; i < 4; i++) {
        m_row[i] = -1e30f;
        l_row[i] = 0.f;
#pragma unroll
        for (int j = 0; j < 4; j++) acc[i][j] = 0.f;
    }

    for (int cidx = 0; cidx < NCHUNK; cidx++) {
        const int sbase = cidx * BS;

        __syncthreads();   // previous PV finished before ks/vs overwritten

        // ---- Load K,V chunk (coalesced along s; OOB -> 0) ----
        for (int idx = tid; idx < CHD * BS; idx += 256) {
            int c = idx >> 6, s = idx & 63;
            int sg = sbase + s;
            float kv = 0.f, vv = 0.f;
            if (sg < SLEN) {
                kv = ekb[c * SLEN + sg];
                vv = evb[c * SLEN + sg];
            } else if (sg < LLEN) {
                int tt = sg - SLEN;
                kv = kb[c * TLEN + tt];
                vv = vb[c * TLEN + tt];
            }
            ks[c * 64 + s]  = kv;
            vs[s * PAD + c] = vv;   // transposed for PV reads
        }
        __syncthreads();

        // ---- S = QK^T + mask : rows t = ty*4+i, cols s = tx*4+j ----
        float sacc[4][4];
#pragma unroll
        for (int i = 0; i < 4; i++) {
            const float* mrow = mask + (size_t)(t0 + ty * 4 + i) * LLEN;
#pragma unroll
            for (int j = 0; j < 4; j++) {
                int sg = sbase + tx * 4 + j;
                sacc[i][j] = (sg < LLEN) ? mrow[sg] : -1e30f;
            }
        }
#pragma unroll 4
        for (int c = 0; c < CHD; c++) {
            float4 q4 = *(const float4*)(qs + c * 64 + ty * 4);
            float4 k4 = *(const float4*)(ks + c * 64 + tx * 4);
            float qv[4] = {q4.x, q4.y, q4.z, q4.w};
            float kv[4] = {k4.x, k4.y, k4.z, k4.w};
#pragma unroll
            for (int i = 0; i < 4; i++)
#pragma unroll
                for (int j = 0; j < 4; j++)
                    sacc[i][j] = fmaf(qv[i], kv[j], sacc[i][j]);
        }

        // ---- Online softmax (row reduction over 16 tx lanes, same warp half) ----
        float p[4][4];
#pragma unroll
        for (int i = 0; i < 4; i++) {
            float mx = fmaxf(fmaxf(sacc[i][0], sacc[i][1]),
                             fmaxf(sacc[i][2], sacc[i][3]));
#pragma unroll
            for (int off = 1; off < 16; off <<= 1)
                mx = fmaxf(mx, __shfl_xor_sync(0xffffffffu, mx, off));
            float mnew  = fmaxf(m_row[i], mx);
            float alpha = __expf(m_row[i] - mnew);
            float rs = 0.f;
#pragma unroll
            for (int j = 0; j < 4; j++) {
                p[i][j] = __expf(sacc[i][j] - mnew);
                rs += p[i][j];
            }
#pragma unroll
            for (int off = 1; off < 16; off <<= 1)
                rs += __shfl_xor_sync(0xffffffffu, rs, off);
            l_row[i] = l_row[i] * alpha + rs;
            m_row[i] = mnew;
            if (tx == 0) al_s[ty * 4 + i] = alpha;
        }
        // Write P transposed: ws[s][t] (vectorized along t)
#pragma unroll
        for (int j = 0; j < 4; j++) {
            float4 w4 = make_float4(p[0][j], p[1][j], p[2][j], p[3][j]);
            *(float4*)(ws + (tx * 4 + j) * PAD + ty * 4) = w4;
        }
        __syncthreads();

        // ---- Rescale O, then O += V @ P^T : rows c = ty*4+i, cols t = tx*4+j ----
#pragma unroll
        for (int j = 0; j < 4; j++) {
            float alpha = al_s[tx * 4 + j];
#pragma unroll
            for (int i = 0; i < 4; i++) acc[i][j] *= alpha;
        }
#pragma unroll 4
        for (int s = 0; s < BS; s++) {
            float4 v4 = *(const float4*)(vs + s * PAD + ty * 4);
            float4 w4 = *(const float4*)(ws + s * PAD + tx * 4);
            float vv[4] = {v4.x, v4.y, v4.z, v4.w};
            float wv[4] = {w4.x, w4.y, w4.z, w4.w};
#pragma unroll
            for (int i = 0; i < 4; i++)
#pragma unroll
                for (int j = 0; j < 4; j++)
                    acc[i][j] = fmaf(vv[i], wv[j], acc[i][j]);
        }
    }

    // ---- Epilogue: publish denominators, normalize, store ----
    if (tx == 0) {
#pragma unroll
        for (int i = 0; i < 4; i++) l_s[ty * 4 + i] = l_row[i];
    }
    __syncthreads();

    float inv[4];
#pragma unroll
    for (int j = 0; j < 4; j++) inv[j] = 1.f / l_s[tx * 4 + j];

    float* ob = out + (size_t)n * CHD * TLEN + t0;
#pragma unroll
    for (int i = 0; i < 4; i++) {
        float4 o = make_float4(acc[i][0] * inv[0], acc[i][1] * inv[1],
                               acc[i][2] * inv[2], acc[i][3] * inv[3]);
        *(float4*)(ob + (ty * 4 + i) * TLEN + tx * 4) = o;
    }
}

extern "C" void kernel_launch(void* const* d_in, const int* in_sizes, int n_in,
                              void* d_out, int out_size)
{
    const float* qkv  = (const float*)d_in[0];   // [32, 192, 2048]
    const float* enc  = (const float*)d_in[1];   // [32, 128, 77]
    const float* mask = (const float*)d_in[2];   // [1, 2048, 2125]
    float* out = (float*)d_out;                  // [32, 64, 2048]

    const size_t smem = SMEM_FLOATS * sizeof(float);   // 68096 B
    cudaFuncSetAttribute(attn_fa32_kernel,
                         cudaFuncAttributeMaxDynamicSharedMemorySize, (int)smem);

    dim3 grid(TLEN / BT, NB);   // (32, 32)
    attn_fa32_kernel<<<grid, 256, smem>>>(qkv, enc, mask, out);
}

// round 6
// speedup vs baseline: 3.5923x; 3.5923x over previous
#include <cuda_runtime.h>
#include <cuda_fp16.h>
#include <stdint.h>

#define NB    32
#define CHD   64
#define TLEN  2048
#define SLEN  77
#define LLEN  (SLEN + TLEN)            // 2125
#define BT    128                      // query rows per block (8 warps x 16)
#define BS    64                       // keys per chunk
#define NCHUNK ((LLEN + BS - 1) / BS)  // 34

#define QS_STRIDE 136                  // halfs per Q smem row (128 + 8 pad)
#define KS_STRIDE 72                   // halfs per K/V smem row (64 + 8 pad)
#define OS_STRIDE 65                   // floats per epilogue row

#define SMEM_Q_BYTES (CHD * QS_STRIDE * 2)            // 17408
#define SMEM_K_BYTES (CHD * KS_STRIDE * 2)            // 9216
#define SMEM_TOTAL   (SMEM_Q_BYTES + 2 * SMEM_K_BYTES) // 35840 (>= 128*65*4 = 33280)

// ---------------- PTX helpers ----------------
static __device__ __forceinline__ uint32_t smem_u32(const void* p) {
    return (uint32_t)__cvta_generic_to_shared(p);
}
static __device__ __forceinline__ void ldsm_x4(uint32_t& r0, uint32_t& r1,
                                               uint32_t& r2, uint32_t& r3, uint32_t a) {
    asm volatile("ldmatrix.sync.aligned.m8n8.x4.shared.b16 {%0,%1,%2,%3}, [%4];"
                 : "=r"(r0), "=r"(r1), "=r"(r2), "=r"(r3) : "r"(a));
}
static __device__ __forceinline__ void ldsm_x4_t(uint32_t& r0, uint32_t& r1,
                                                 uint32_t& r2, uint32_t& r3, uint32_t a) {
    asm volatile("ldmatrix.sync.aligned.m8n8.x4.trans.shared.b16 {%0,%1,%2,%3}, [%4];"
                 : "=r"(r0), "=r"(r1), "=r"(r2), "=r"(r3) : "r"(a));
}
static __device__ __forceinline__ void mma16816(float* d,
                                                uint32_t a0, uint32_t a1, uint32_t a2, uint32_t a3,
                                                uint32_t b0, uint32_t b1) {
    asm volatile("mma.sync.aligned.m16n8k16.row.col.f32.f16.f16.f32 "
                 "{%0,%1,%2,%3},{%4,%5,%6,%7},{%8,%9},{%0,%1,%2,%3};"
                 : "+f"(d[0]), "+f"(d[1]), "+f"(d[2]), "+f"(d[3])
                 : "r"(a0), "r"(a1), "r"(a2), "r"(a3), "r"(b0), "r"(b1));
}
static __device__ __forceinline__ uint32_t pack_h2(float x, float y) {
    __half2 h = __floats2half2_rn(x, y);
    return *reinterpret_cast<uint32_t*>(&h);
}

// ---------------- kernel ----------------
__global__ void __launch_bounds__(256)
attn_fa16_kernel(const float* __restrict__ qkv,
                 const float* __restrict__ enc,
                 const float* __restrict__ mask,
                 float* __restrict__ out)
{
    extern __shared__ char smraw[];
    __half* Qs = (__half*)smraw;                            // [64][136] : [c][t]
    __half* Ks = (__half*)(smraw + SMEM_Q_BYTES);           // [64][72]  : [c][s]
    __half* Vs = (__half*)(smraw + SMEM_Q_BYTES + SMEM_K_BYTES); // [64][72] : [c][s]
    float*  Os = (float*)smraw;                             // [128][65] : [t][c] (epilogue)

    const int tid  = threadIdx.x;
    const int wid  = tid >> 5;
    const int lane = tid & 31;
    const int g    = lane >> 2;      // fragment row group 0..7
    const int tg   = lane & 3;       // fragment col group 0..3
    const int n    = blockIdx.y;
    const int t0   = blockIdx.x * BT;
    const int tw   = wid * 16;       // this warp's t-row offset within tile

    const float* qb  = qkv + (size_t)n * (3 * CHD * TLEN);
    const float* kb  = qb + CHD * TLEN;
    const float* vb  = qb + 2 * CHD * TLEN;
    const float* ekb = enc + (size_t)n * (2 * CHD * SLEN);
    const float* evb = ekb + CHD * SLEN;

    // ---- Load Q tile: q[c][t0+t] * 0.125 -> Qs[c][t] (fp16) ----
    for (int idx = tid; idx < CHD * (BT / 2); idx += 256) {
        int c = idx >> 6, t2 = idx & 63;     // t2: half2 index along t
        float2 q2 = *(const float2*)(qb + c * TLEN + t0 + t2 * 2);
        *(__half2*)(Qs + c * QS_STRIDE + t2 * 2) =
            __floats2half2_rn(q2.x * 0.125f, q2.y * 0.125f);
    }
    __syncthreads();

    // ---- Q fragments, register-resident for all chunks: qf[kstep][4] ----
    uint32_t qf[4][4];
#pragma unroll
    for (int k = 0; k < 4; k++) {
        int c_row = k * 16 + (lane & 7) + ((lane & 16) ? 8 : 0);
        int t_col = tw + ((lane & 8) ? 8 : 0);
        ldsm_x4_t(qf[k][0], qf[k][1], qf[k][2], qf[k][3],
                  smem_u32(Qs + c_row * QS_STRIDE + t_col));
    }

    // ---- online softmax state + output accumulators ----
    float m0 = -1e30f, m1 = -1e30f, l0 = 0.f, l1 = 0.f;
    float oacc[8][4];
#pragma unroll
    for (int i = 0; i < 8; i++)
#pragma unroll
        for (int j = 0; j < 4; j++) oacc[i][j] = 0.f;

    const int row0 = t0 + tw + g;    // global query rows: row0, row0+8
    const float* mrowA = mask + (size_t)row0 * LLEN;
    const float* mrowB = mask + (size_t)(row0 + 8) * LLEN;

    for (int chunk = 0; chunk < NCHUNK; chunk++) {
        const int sbase = chunk * BS;
        __syncthreads();

        // ---- load K,V chunk -> Ks/Vs [c][s] fp16 (OOB -> 0) ----
        const bool inner = (sbase >= SLEN) && (sbase + BS <= LLEN);
        for (int idx = tid; idx < CHD * (BS / 2); idx += 256) {
            int c = idx >> 5, s2 = idx & 31;
            int sg = sbase + s2 * 2;
            float k0, k1, v0, v1;
            if (inner) {
                int o = c * TLEN + (sg - SLEN);
                k0 = kb[o]; k1 = kb[o + 1];
                v0 = vb[o]; v1 = vb[o + 1];
            } else {
                k0 = k1 = v0 = v1 = 0.f;
                if (sg < SLEN)           { k0 = ekb[c * SLEN + sg];       v0 = evb[c * SLEN + sg]; }
                else if (sg < LLEN)      { k0 = kb[c * TLEN + sg - SLEN]; v0 = vb[c * TLEN + sg - SLEN]; }
                int sg1 = sg + 1;
                if (sg1 < SLEN)          { k1 = ekb[c * SLEN + sg1];       v1 = evb[c * SLEN + sg1]; }
                else if (sg1 < LLEN)     { k1 = kb[c * TLEN + sg1 - SLEN]; v1 = vb[c * TLEN + sg1 - SLEN]; }
            }
            *(__half2*)(Ks + c * KS_STRIDE + s2 * 2) = __floats2half2_rn(k0, k1);
            *(__half2*)(Vs + c * KS_STRIDE + s2 * 2) = __floats2half2_rn(v0, v1);
        }
        __syncthreads();

        // ---- S = Q K^T (+mask) : sacc[n8][4] covers rows {g,g+8}, cols n8*8 + 2tg,+1 ----
        // NOTE: LLEN=2125 is odd, so mask rows alternate float2 alignment —
        // scalar loads only here (round-2 failure was a misaligned float2).
        float sacc[8][4];
        const bool tail = (sbase + BS > LLEN);
#pragma unroll
        for (int nn = 0; nn < 8; nn++) {
            int col = sbase + nn * 8 + tg * 2;
            if (!tail) {
                sacc[nn][0] = mrowA[col];
                sacc[nn][1] = mrowA[col + 1];
                sacc[nn][2] = mrowB[col];
                sacc[nn][3] = mrowB[col + 1];
            } else {
                sacc[nn][0] = (col     < LLEN) ? mrowA[col]     : -1e30f;
                sacc[nn][1] = (col + 1 < LLEN) ? mrowA[col + 1] : -1e30f;
                sacc[nn][2] = (col     < LLEN) ? mrowB[col]     : -1e30f;
                sacc[nn][3] = (col + 1 < LLEN) ? mrowB[col + 1] : -1e30f;
            }
        }
#pragma unroll
        for (int nn = 0; nn < 8; nn++) {
#pragma unroll
            for (int kk = 0; kk < 2; kk++) {
                uint32_t b0, b1, b2, b3;
                int c_row = kk * 32 + ((lane >> 3) << 3) + (lane & 7);
                ldsm_x4_t(b0, b1, b2, b3, smem_u32(Ks + c_row * KS_STRIDE + nn * 8));
                mma16816(sacc[nn], qf[2*kk][0],   qf[2*kk][1],   qf[2*kk][2],   qf[2*kk][3],   b0, b1);
                mma16816(sacc[nn], qf[2*kk+1][0], qf[2*kk+1][1], qf[2*kk+1][2], qf[2*kk+1][3], b2, b3);
            }
        }

        // ---- online softmax over the 64 chunk columns (rows g and g+8) ----
        float rmax0 = -1e30f, rmax1 = -1e30f;
#pragma unroll
        for (int nn = 0; nn < 8; nn++) {
            rmax0 = fmaxf(rmax0, fmaxf(sacc[nn][0], sacc[nn][1]));
            rmax1 = fmaxf(rmax1, fmaxf(sacc[nn][2], sacc[nn][3]));
        }
        rmax0 = fmaxf(rmax0, __shfl_xor_sync(0xffffffffu, rmax0, 1));
        rmax0 = fmaxf(rmax0, __shfl_xor_sync(0xffffffffu, rmax0, 2));
        rmax1 = fmaxf(rmax1, __shfl_xor_sync(0xffffffffu, rmax1, 1));
        rmax1 = fmaxf(rmax1, __shfl_xor_sync(0xffffffffu, rmax1, 2));

        float mn0 = fmaxf(m0, rmax0), mn1 = fmaxf(m1, rmax1);
        float al0 = __expf(m0 - mn0), al1 = __expf(m1 - mn1);
        float rs0 = 0.f, rs1 = 0.f;
#pragma unroll
        for (int nn = 0; nn < 8; nn++) {
            sacc[nn][0] = __expf(sacc[nn][0] - mn0);
            sacc[nn][1] = __expf(sacc[nn][1] - mn0);
            sacc[nn][2] = __expf(sacc[nn][2] - mn1);
            sacc[nn][3] = __expf(sacc[nn][3] - mn1);
            rs0 += sacc[nn][0] + sacc[nn][1];
            rs1 += sacc[nn][2] + sacc[nn][3];
        }
        rs0 += __shfl_xor_sync(0xffffffffu, rs0, 1);
        rs0 += __shfl_xor_sync(0xffffffffu, rs0, 2);
        rs1 += __shfl_xor_sync(0xffffffffu, rs1, 1);
        rs1 += __shfl_xor_sync(0xffffffffu, rs1, 2);
        l0 = l0 * al0 + rs0;  m0 = mn0;
        l1 = l1 * al1 + rs1;  m1 = mn1;

        // rescale O
#pragma unroll
        for (int nn = 0; nn < 8; nn++) {
            oacc[nn][0] *= al0; oacc[nn][1] *= al0;
            oacc[nn][2] *= al1; oacc[nn][3] *= al1;
        }

        // ---- P fragments (A of PV), k'=0..3 each spans S tiles {2k',2k'+1} ----
        uint32_t pf[4][4];
#pragma unroll
        for (int kp = 0; kp < 4; kp++) {
            pf[kp][0] = pack_h2(sacc[2*kp][0],   sacc[2*kp][1]);
            pf[kp][1] = pack_h2(sacc[2*kp][2],   sacc[2*kp][3]);
            pf[kp][2] = pack_h2(sacc[2*kp+1][0], sacc[2*kp+1][1]);
            pf[kp][3] = pack_h2(sacc[2*kp+1][2], sacc[2*kp+1][3]);
        }

        // ---- O += P V^T : cols c = np*8 + 2tg ----
#pragma unroll
        for (int np = 0; np < 8; np++) {
#pragma unroll
            for (int kk = 0; kk < 2; kk++) {
                uint32_t b0, b1, b2, b3;
                int c_row = np * 8 + (lane & 7);
                int s_col = kk * 32 + ((lane >> 3) << 3);
                ldsm_x4(b0, b1, b2, b3, smem_u32(Vs + c_row * KS_STRIDE + s_col));
                mma16816(oacc[np], pf[2*kk][0],   pf[2*kk][1],   pf[2*kk][2],   pf[2*kk][3],   b0, b1);
                mma16816(oacc[np], pf[2*kk+1][0], pf[2*kk+1][1], pf[2*kk+1][2], pf[2*kk+1][3], b2, b3);
            }
        }
    }

    // ---- epilogue: normalize, stage [t][c] in smem, coalesced transpose store ----
    __syncthreads();   // done reading Ks/Vs/Qs before overwriting with Os
    float inv0 = 1.f / l0, inv1 = 1.f / l1;
#pragma unroll
    for (int np = 0; np < 8; np++) {
        int c = np * 8 + tg * 2;
        Os[(tw + g)     * OS_STRIDE + c]     = oacc[np][0] * inv0;
        Os[(tw + g)     * OS_STRIDE + c + 1] = oacc[np][1] * inv0;
        Os[(tw + g + 8) * OS_STRIDE + c]     = oacc[np][2] * inv1;
        Os[(tw + g + 8) * OS_STRIDE + c + 1] = oacc[np][3] * inv1;
    }
    __syncthreads();

    float* ob = out + (size_t)n * CHD * TLEN + t0;
    for (int idx = tid; idx < CHD * BT; idx += 256) {
        int c = idx >> 7, t = idx & 127;
        ob[c * TLEN + t] = Os[t * OS_STRIDE + c];
    }
}

extern "C" void kernel_launch(void* const* d_in, const int* in_sizes, int n_in,
                              void* d_out, int out_size)
{
    const float* qkv  = (const float*)d_in[0];   // [32, 192, 2048]
    const float* enc  = (const float*)d_in[1];   // [32, 128, 77]
    const float* mask = (const float*)d_in[2];   // [1, 2048, 2125]
    float* out = (float*)d_out;                  // [32, 64, 2048]

    dim3 grid(TLEN / BT, NB);   // (16, 32)
    attn_fa16_kernel<<<grid, 256, SMEM_TOTAL>>>(qkv, enc, mask, out);
}

// round 7
// speedup vs baseline: 6.2273x; 1.7335x over previous
#include <cuda_runtime.h>
#include <cuda_fp16.h>
#include <stdint.h>

#define NB    32
#define CHD   64
#define TLEN  2048
#define SLEN  77
#define LLEN  (SLEN + TLEN)            // 2125
#define BT    128                      // query rows per block (8 warps x 16)
#define BS    64                       // keys per chunk
#define NCHUNK ((LLEN + BS - 1) / BS)  // 34
#define SP    (NCHUNK * BS)            // 2176: padded key length (zero tail)

#define QS_STRIDE 136                  // halfs per Q smem row (128 + 8 pad)
#define KS_STRIDE 72                   // halfs per K/V smem row (64+8; 144B = 16B-aligned)
#define OS_STRIDE 65                   // floats per epilogue row

#define SMEM_Q_BYTES (CHD * QS_STRIDE * 2)            // 17408
#define SMEM_K_BYTES (CHD * KS_STRIDE * 2)            // 9216
#define SMEM_TOTAL   (SMEM_Q_BYTES + 4 * SMEM_K_BYTES) // 54272 (Os needs 33280, overlays)

// fp16 pre-converted K/V scratch: [n][c][SP], s zero-padded
__device__ __half g_Kh[NB * CHD * SP];
__device__ __half g_Vh[NB * CHD * SP];

// ---------------- PTX helpers ----------------
static __device__ __forceinline__ uint32_t smem_u32(const void* p) {
    return (uint32_t)__cvta_generic_to_shared(p);
}
static __device__ __forceinline__ void cpa16(uint32_t dst, const void* src) {
    asm volatile("cp.async.cg.shared.global [%0], [%1], 16;" :: "r"(dst), "l"(src));
}
static __device__ __forceinline__ void cpa_wait_all() {
    asm volatile("cp.async.wait_all;" ::: "memory");
}
static __device__ __forceinline__ void ldsm_x4(uint32_t& r0, uint32_t& r1,
                                               uint32_t& r2, uint32_t& r3, uint32_t a) {
    asm volatile("ldmatrix.sync.aligned.m8n8.x4.shared.b16 {%0,%1,%2,%3}, [%4];"
                 : "=r"(r0), "=r"(r1), "=r"(r2), "=r"(r3) : "r"(a));
}
static __device__ __forceinline__ void ldsm_x4_t(uint32_t& r0, uint32_t& r1,
                                                 uint32_t& r2, uint32_t& r3, uint32_t a) {
    asm volatile("ldmatrix.sync.aligned.m8n8.x4.trans.shared.b16 {%0,%1,%2,%3}, [%4];"
                 : "=r"(r0), "=r"(r1), "=r"(r2), "=r"(r3) : "r"(a));
}
static __device__ __forceinline__ void mma16816(float* d,
                                                uint32_t a0, uint32_t a1, uint32_t a2, uint32_t a3,
                                                uint32_t b0, uint32_t b1) {
    asm volatile("mma.sync.aligned.m16n8k16.row.col.f32.f16.f16.f32 "
                 "{%0,%1,%2,%3},{%4,%5,%6,%7},{%8,%9},{%0,%1,%2,%3};"
                 : "+f"(d[0]), "+f"(d[1]), "+f"(d[2]), "+f"(d[3])
                 : "r"(a0), "r"(a1), "r"(a2), "r"(a3), "r"(b0), "r"(b1));
}
static __device__ __forceinline__ uint32_t pack_h2(float x, float y) {
    __half2 h = __floats2half2_rn(x, y);
    return *reinterpret_cast<uint32_t*>(&h);
}

// ---------------- prologue: build fp16 K/V with concat + zero pad ----------------
__global__ void __launch_bounds__(256)
convert_kv_kernel(const float* __restrict__ qkv, const float* __restrict__ enc)
{
    int idx = blockIdx.x * 256 + threadIdx.x;       // over NB*CHD*SP
    if (idx >= NB * CHD * SP) return;
    int s  = idx % SP;
    int nc = idx / SP;
    int c  = nc % CHD;
    int n  = nc / CHD;
    const float* qb  = qkv + (size_t)n * (3 * CHD * TLEN);
    const float* ekb = enc + (size_t)n * (2 * CHD * SLEN);
    float k = 0.f, v = 0.f;
    if (s < SLEN) {
        k = ekb[c * SLEN + s];
        v = ekb[(CHD + c) * SLEN + s];
    } else if (s < LLEN) {
        k = qb[(CHD + c) * TLEN + (s - SLEN)];
        v = qb[(2 * CHD + c) * TLEN + (s - SLEN)];
    }
    g_Kh[idx] = __float2half(k);
    g_Vh[idx] = __float2half(v);
}

// ---------------- main attention kernel ----------------
__global__ void __launch_bounds__(256, 2)
attn_fa16_kernel(const float* __restrict__ qkv,
                 const float* __restrict__ mask,
                 float* __restrict__ out)
{
    extern __shared__ char smraw[];
    __half* Qs = (__half*)smraw;                    // [64][136] : [c][t]
    __half* KVs = (__half*)(smraw + SMEM_Q_BYTES);  // 4 buffers: K0,V0,K1,V1 (each 64x72)
    float*  Os = (float*)smraw;                     // [128][65] : [t][c] (epilogue overlay)

    const int tid  = threadIdx.x;
    const int wid  = tid >> 5;
    const int lane = tid & 31;
    const int g    = lane >> 2;
    const int tg   = lane & 3;
    const int n    = blockIdx.y;
    const int t0   = blockIdx.x * BT;
    const int tw   = wid * 16;

    const float*  qb  = qkv + (size_t)n * (3 * CHD * TLEN);
    const __half* Khn = g_Kh + (size_t)n * CHD * SP;
    const __half* Vhn = g_Vh + (size_t)n * CHD * SP;

    // issue cp.async for chunk `cn` into buffer `buf` (K + V tiles, 16KB total)
    auto issue_chunk = [&](int cn, int buf) {
        if (cn >= NCHUNK) return;
        const int sb = cn * BS;
        __half* Kd = KVs + buf * (2 * CHD * KS_STRIDE);
        __half* Vd = Kd + CHD * KS_STRIDE;
#pragma unroll
        for (int i = tid; i < 512; i += 256) {
            int r = i >> 3, sg = (i & 7) * 8;
            cpa16(smem_u32(Kd + r * KS_STRIDE + sg), Khn + r * SP + sb + sg);
            cpa16(smem_u32(Vd + r * KS_STRIDE + sg), Vhn + r * SP + sb + sg);
        }
    };

    issue_chunk(0, 0);

    // ---- Load Q tile: q[c][t0+t] * 0.125 -> Qs[c][t] (fp16) ----
    for (int idx = tid; idx < CHD * (BT / 2); idx += 256) {
        int c = idx >> 6, t2 = idx & 63;
        float2 q2 = *(const float2*)(qb + c * TLEN + t0 + t2 * 2);
        *(__half2*)(Qs + c * QS_STRIDE + t2 * 2) =
            __floats2half2_rn(q2.x * 0.125f, q2.y * 0.125f);
    }
    __syncthreads();

    // ---- Q fragments, register-resident across all chunks ----
    uint32_t qf[4][4];
#pragma unroll
    for (int k = 0; k < 4; k++) {
        int c_row = k * 16 + (lane & 7) + ((lane & 16) ? 8 : 0);
        int t_col = tw + ((lane & 8) ? 8 : 0);
        ldsm_x4_t(qf[k][0], qf[k][1], qf[k][2], qf[k][3],
                  smem_u32(Qs + c_row * QS_STRIDE + t_col));
    }

    float m0 = -1e30f, m1 = -1e30f, l0 = 0.f, l1 = 0.f;
    float oacc[8][4];
#pragma unroll
    for (int i = 0; i < 8; i++)
#pragma unroll
        for (int j = 0; j < 4; j++) oacc[i][j] = 0.f;

    const int row0 = t0 + tw + g;
    const float* mrowA = mask + (size_t)row0 * LLEN;
    const float* mrowB = mask + (size_t)(row0 + 8) * LLEN;

    for (int chunk = 0; chunk < NCHUNK; chunk++) {
        const int cur = chunk & 1;
        const int sbase = chunk * BS;
        const __half* Kc = KVs + cur * (2 * CHD * KS_STRIDE);
        const __half* Vc = Kc + CHD * KS_STRIDE;

        cpa_wait_all();        // chunk data arrived
        __syncthreads();       // visible block-wide; prev compute done (program order)
        issue_chunk(chunk + 1, cur ^ 1);   // overlap next load with this compute

        // ---- mask loads hoisted (latency hides under the MMAs below) ----
        // LLEN=2125 odd -> scalar loads only (alignment).
        float macc[8][4];
        const bool tail = (sbase + BS > LLEN);
#pragma unroll
        for (int nn = 0; nn < 8; nn++) {
            int col = sbase + nn * 8 + tg * 2;
            if (!tail) {
                macc[nn][0] = mrowA[col];
                macc[nn][1] = mrowA[col + 1];
                macc[nn][2] = mrowB[col];
                macc[nn][3] = mrowB[col + 1];
            } else {
                macc[nn][0] = (col     < LLEN) ? mrowA[col]     : -1e30f;
                macc[nn][1] = (col + 1 < LLEN) ? mrowA[col + 1] : -1e30f;
                macc[nn][2] = (col     < LLEN) ? mrowB[col]     : -1e30f;
                macc[nn][3] = (col + 1 < LLEN) ? mrowB[col + 1] : -1e30f;
            }
        }

        // ---- S = Q K^T ----
        float sacc[8][4];
#pragma unroll
        for (int nn = 0; nn < 8; nn++) {
            sacc[nn][0] = 0.f; sacc[nn][1] = 0.f; sacc[nn][2] = 0.f; sacc[nn][3] = 0.f;
#pragma unroll
            for (int kk = 0; kk < 2; kk++) {
                uint32_t b0, b1, b2, b3;
                int c_row = kk * 32 + ((lane >> 3) << 3) + (lane & 7);
                ldsm_x4_t(b0, b1, b2, b3, smem_u32(Kc + c_row * KS_STRIDE + nn * 8));
                mma16816(sacc[nn], qf[2*kk][0],   qf[2*kk][1],   qf[2*kk][2],   qf[2*kk][3],   b0, b1);
                mma16816(sacc[nn], qf[2*kk+1][0], qf[2*kk+1][1], qf[2*kk+1][2], qf[2*kk+1][3], b2, b3);
            }
            sacc[nn][0] += macc[nn][0];
            sacc[nn][1] += macc[nn][1];
            sacc[nn][2] += macc[nn][2];
            sacc[nn][3] += macc[nn][3];
        }

        // ---- online softmax (rows g, g+8) ----
        float rmax0 = -1e30f, rmax1 = -1e30f;
#pragma unroll
        for (int nn = 0; nn < 8; nn++) {
            rmax0 = fmaxf(rmax0, fmaxf(sacc[nn][0], sacc[nn][1]));
            rmax1 = fmaxf(rmax1, fmaxf(sacc[nn][2], sacc[nn][3]));
        }
        rmax0 = fmaxf(rmax0, __shfl_xor_sync(0xffffffffu, rmax0, 1));
        rmax0 = fmaxf(rmax0, __shfl_xor_sync(0xffffffffu, rmax0, 2));
        rmax1 = fmaxf(rmax1, __shfl_xor_sync(0xffffffffu, rmax1, 1));
        rmax1 = fmaxf(rmax1, __shfl_xor_sync(0xffffffffu, rmax1, 2));

        float mn0 = fmaxf(m0, rmax0), mn1 = fmaxf(m1, rmax1);
        float al0 = __expf(m0 - mn0), al1 = __expf(m1 - mn1);
        float rs0 = 0.f, rs1 = 0.f;
#pragma unroll
        for (int nn = 0; nn < 8; nn++) {
            sacc[nn][0] = __expf(sacc[nn][0] - mn0);
            sacc[nn][1] = __expf(sacc[nn][1] - mn0);
            sacc[nn][2] = __expf(sacc[nn][2] - mn1);
            sacc[nn][3] = __expf(sacc[nn][3] - mn1);
            rs0 += sacc[nn][0] + sacc[nn][1];
            rs1 += sacc[nn][2] + sacc[nn][3];
        }
        rs0 += __shfl_xor_sync(0xffffffffu, rs0, 1);
        rs0 += __shfl_xor_sync(0xffffffffu, rs0, 2);
        rs1 += __shfl_xor_sync(0xffffffffu, rs1, 1);
        rs1 += __shfl_xor_sync(0xffffffffu, rs1, 2);
        l0 = l0 * al0 + rs0;  m0 = mn0;
        l1 = l1 * al1 + rs1;  m1 = mn1;

#pragma unroll
        for (int nn = 0; nn < 8; nn++) {
            oacc[nn][0] *= al0; oacc[nn][1] *= al0;
            oacc[nn][2] *= al1; oacc[nn][3] *= al1;
        }

        // ---- P fragments ----
        uint32_t pf[4][4];
#pragma unroll
        for (int kp = 0; kp < 4; kp++) {
            pf[kp][0] = pack_h2(sacc[2*kp][0],   sacc[2*kp][1]);
            pf[kp][1] = pack_h2(sacc[2*kp][2],   sacc[2*kp][3]);
            pf[kp][2] = pack_h2(sacc[2*kp+1][0], sacc[2*kp+1][1]);
            pf[kp][3] = pack_h2(sacc[2*kp+1][2], sacc[2*kp+1][3]);
        }

        // ---- O += P V^T ----
#pragma unroll
        for (int np = 0; np < 8; np++) {
#pragma unroll
            for (int kk = 0; kk < 2; kk++) {
                uint32_t b0, b1, b2, b3;
                int c_row = np * 8 + (lane & 7);
                int s_col = kk * 32 + ((lane >> 3) << 3);
                ldsm_x4(b0, b1, b2, b3, smem_u32(Vc + c_row * KS_STRIDE + s_col));
                mma16816(oacc[np], pf[2*kk][0],   pf[2*kk][1],   pf[2*kk][2],   pf[2*kk][3],   b0, b1);
                mma16816(oacc[np], pf[2*kk+1][0], pf[2*kk+1][1], pf[2*kk+1][2], pf[2*kk+1][3], b2, b3);
            }
        }
    }

    // ---- epilogue ----
    __syncthreads();
    float inv0 = 1.f / l0, inv1 = 1.f / l1;
#pragma unroll
    for (int np = 0; np < 8; np++) {
        int c = np * 8 + tg * 2;
        Os[(tw + g)     * OS_STRIDE + c]     = oacc[np][0] * inv0;
        Os[(tw + g)     * OS_STRIDE + c + 1] = oacc[np][1] * inv0;
        Os[(tw + g + 8) * OS_STRIDE + c]     = oacc[np][2] * inv1;
        Os[(tw + g + 8) * OS_STRIDE + c + 1] = oacc[np][3] * inv1;
    }
    __syncthreads();

    float* ob = out + (size_t)n * CHD * TLEN + t0;
    for (int idx = tid; idx < CHD * BT; idx += 256) {
        int c = idx >> 7, t = idx & 127;
        ob[c * TLEN + t] = Os[t * OS_STRIDE + c];
    }
}

extern "C" void kernel_launch(void* const* d_in, const int* in_sizes, int n_in,
                              void* d_out, int out_size)
{
    const float* qkv  = (const float*)d_in[0];   // [32, 192, 2048]
    const float* enc  = (const float*)d_in[1];   // [32, 128, 77]
    const float* mask = (const float*)d_in[2];   // [1, 2048, 2125]
    float* out = (float*)d_out;                  // [32, 64, 2048]

    int nconv = NB * CHD * SP;
    convert_kv_kernel<<<(nconv + 255) / 256, 256>>>(qkv, enc);

    cudaFuncSetAttribute(attn_fa16_kernel,
                         cudaFuncAttributeMaxDynamicSharedMemorySize, SMEM_TOTAL);
    dim3 grid(TLEN / BT, NB);   // (16, 32)
    attn_fa16_kernel<<<grid, 256, SMEM_TOTAL>>>(qkv, mask, out);
}

// round 8
// speedup vs baseline: 6.7974x; 1.0915x over previous
#include <cuda_runtime.h>
#include <cuda_fp16.h>
#include <stdint.h>

#define NB    32
#define CHD   64
#define TLEN  2048
#define SLEN  77
#define LLEN  (SLEN + TLEN)            // 2125
#define BT    128                      // query rows per block (8 warps x 16)
#define BS    128                      // keys per load chunk (2 x 64 subtiles)
#define NCHUNK ((LLEN + BS - 1) / BS)  // 17
#define SP    (NCHUNK * BS)            // 2176: padded key length (zero tail)

#define QS_STRIDE 136                  // halfs per Q smem row (128 + 8 pad)
#define KS_STRIDE 136                  // halfs per K/V smem row (128+8; 272B, 16B-aligned)
#define OS_STRIDE 65                   // floats per epilogue row

#define SMEM_Q_BYTES (CHD * QS_STRIDE * 2)             // 17408
#define SMEM_K_BYTES (CHD * KS_STRIDE * 2)             // 17408
#define SMEM_TOTAL   (SMEM_Q_BYTES + 4 * SMEM_K_BYTES) // 87040 (Os 33280 overlays)

// fp16 pre-converted K/V scratch: [n][c][SP], s zero-padded
__device__ __half g_Kh[NB * CHD * SP];
__device__ __half g_Vh[NB * CHD * SP];

// ---------------- PTX helpers ----------------
static __device__ __forceinline__ uint32_t smem_u32(const void* p) {
    return (uint32_t)__cvta_generic_to_shared(p);
}
static __device__ __forceinline__ void cpa16(uint32_t dst, const void* src) {
    asm volatile("cp.async.cg.shared.global [%0], [%1], 16;" :: "r"(dst), "l"(src));
}
static __device__ __forceinline__ void cpa_wait_all() {
    asm volatile("cp.async.wait_all;" ::: "memory");
}
static __device__ __forceinline__ void ldsm_x4(uint32_t& r0, uint32_t& r1,
                                               uint32_t& r2, uint32_t& r3, uint32_t a) {
    asm volatile("ldmatrix.sync.aligned.m8n8.x4.shared.b16 {%0,%1,%2,%3}, [%4];"
                 : "=r"(r0), "=r"(r1), "=r"(r2), "=r"(r3) : "r"(a));
}
static __device__ __forceinline__ void ldsm_x4_t(uint32_t& r0, uint32_t& r1,
                                                 uint32_t& r2, uint32_t& r3, uint32_t a) {
    asm volatile("ldmatrix.sync.aligned.m8n8.x4.trans.shared.b16 {%0,%1,%2,%3}, [%4];"
                 : "=r"(r0), "=r"(r1), "=r"(r2), "=r"(r3) : "r"(a));
}
static __device__ __forceinline__ void mma16816(float* d,
                                                uint32_t a0, uint32_t a1, uint32_t a2, uint32_t a3,
                                                uint32_t b0, uint32_t b1) {
    asm volatile("mma.sync.aligned.m16n8k16.row.col.f32.f16.f16.f32 "
                 "{%0,%1,%2,%3},{%4,%5,%6,%7},{%8,%9},{%0,%1,%2,%3};"
                 : "+f"(d[0]), "+f"(d[1]), "+f"(d[2]), "+f"(d[3])
                 : "r"(a0), "r"(a1), "r"(a2), "r"(a3), "r"(b0), "r"(b1));
}
static __device__ __forceinline__ uint32_t pack_h2(float x, float y) {
    __half2 h = __floats2half2_rn(x, y);
    return *reinterpret_cast<uint32_t*>(&h);
}

// ---------------- prologue: build fp16 K/V with concat + zero pad ----------------
__global__ void __launch_bounds__(256)
convert_kv_kernel(const float* __restrict__ qkv, const float* __restrict__ enc)
{
    int idx = blockIdx.x * 256 + threadIdx.x;       // over NB*CHD*SP
    if (idx >= NB * CHD * SP) return;
    int s  = idx % SP;
    int nc = idx / SP;
    int c  = nc % CHD;
    int n  = nc / CHD;
    const float* qb  = qkv + (size_t)n * (3 * CHD * TLEN);
    const float* ekb = enc + (size_t)n * (2 * CHD * SLEN);
    float k = 0.f, v = 0.f;
    if (s < SLEN) {
        k = ekb[c * SLEN + s];
        v = ekb[(CHD + c) * SLEN + s];
    } else if (s < LLEN) {
        k = qb[(CHD + c) * TLEN + (s - SLEN)];
        v = qb[(2 * CHD + c) * TLEN + (s - SLEN)];
    }
    g_Kh[idx] = __float2half(k);
    g_Vh[idx] = __float2half(v);
}

// ---------------- main attention kernel ----------------
__global__ void __launch_bounds__(256, 2)
attn_fa16_kernel(const float* __restrict__ qkv,
                 const float* __restrict__ mask,
                 float* __restrict__ out)
{
    extern __shared__ char smraw[];
    __half* Qs  = (__half*)smraw;                   // [64][136] : [c][t]
    __half* KVs = (__half*)(smraw + SMEM_Q_BYTES);  // 4 buffers: K0,V0,K1,V1 (each 64x136)
    float*  Os  = (float*)smraw;                    // [128][65] : [t][c] (epilogue overlay)

    const int tid  = threadIdx.x;
    const int wid  = tid >> 5;
    const int lane = tid & 31;
    const int g    = lane >> 2;
    const int tg   = lane & 3;
    const int n    = blockIdx.y;
    const int t0   = blockIdx.x * BT;
    const int tw   = wid * 16;

    const float*  qb  = qkv + (size_t)n * (3 * CHD * TLEN);
    const __half* Khn = g_Kh + (size_t)n * CHD * SP;
    const __half* Vhn = g_Vh + (size_t)n * CHD * SP;

    // issue cp.async for 128-key chunk `cn` into buffer `buf` (K + V, 64KB)
    auto issue_chunk = [&](int cn, int buf) {
        if (cn >= NCHUNK) return;
        const int sb = cn * BS;
        __half* Kd = KVs + buf * (2 * CHD * KS_STRIDE);
        __half* Vd = Kd + CHD * KS_STRIDE;
#pragma unroll
        for (int i = tid; i < 1024; i += 256) {
            int r = i >> 4, sg = (i & 15) * 8;
            cpa16(smem_u32(Kd + r * KS_STRIDE + sg), Khn + r * SP + sb + sg);
            cpa16(smem_u32(Vd + r * KS_STRIDE + sg), Vhn + r * SP + sb + sg);
        }
    };

    issue_chunk(0, 0);

    // ---- Load Q tile: q[c][t0+t] * 0.125 -> Qs[c][t] (fp16) ----
    for (int idx = tid; idx < CHD * (BT / 2); idx += 256) {
        int c = idx >> 6, t2 = idx & 63;
        float2 q2 = *(const float2*)(qb + c * TLEN + t0 + t2 * 2);
        *(__half2*)(Qs + c * QS_STRIDE + t2 * 2) =
            __floats2half2_rn(q2.x * 0.125f, q2.y * 0.125f);
    }
    __syncthreads();

    // ---- Q fragments, register-resident across all chunks ----
    uint32_t qf[4][4];
#pragma unroll
    for (int k = 0; k < 4; k++) {
        int c_row = k * 16 + (lane & 7) + ((lane & 16) ? 8 : 0);
        int t_col = tw + ((lane & 8) ? 8 : 0);
        ldsm_x4_t(qf[k][0], qf[k][1], qf[k][2], qf[k][3],
                  smem_u32(Qs + c_row * QS_STRIDE + t_col));
    }

    float m0 = -1e30f, m1 = -1e30f, l0 = 0.f, l1 = 0.f;
    float oacc[8][4];
#pragma unroll
    for (int i = 0; i < 8; i++)
#pragma unroll
        for (int j = 0; j < 4; j++) oacc[i][j] = 0.f;

    const int row0 = t0 + tw + g;
    const float* mrowA = mask + (size_t)row0 * LLEN;
    const float* mrowB = mask + (size_t)(row0 + 8) * LLEN;

    for (int chunk = 0; chunk < NCHUNK; chunk++) {
        const int cur = chunk & 1;
        const __half* Kc = KVs + cur * (2 * CHD * KS_STRIDE);
        const __half* Vc = Kc + CHD * KS_STRIDE;

        cpa_wait_all();        // this chunk's data arrived
        __syncthreads();       // visible block-wide; prev compute done
        issue_chunk(chunk + 1, cur ^ 1);   // overlap next load with this compute

        // Two 64-key subtiles in one unrolled block: subtile 1's LDSM/MMA
        // stream is independent of subtile 0's softmax chain -> ILP across it.
#pragma unroll
        for (int sub = 0; sub < 2; sub++) {
            const int sbase = chunk * BS + sub * 64;
            const __half* Kt = Kc + sub * 64;
            const __half* Vt = Vc + sub * 64;

            // ---- mask loads hoisted (hide under MMAs); LLEN odd -> scalar ----
            float macc[8][4];
            const bool tail = (sbase + 64 > LLEN);
#pragma unroll
            for (int nn = 0; nn < 8; nn++) {
                int col = sbase + nn * 8 + tg * 2;
                if (!tail) {
                    macc[nn][0] = mrowA[col];
                    macc[nn][1] = mrowA[col + 1];
                    macc[nn][2] = mrowB[col];
                    macc[nn][3] = mrowB[col + 1];
                } else {
                    macc[nn][0] = (col     < LLEN) ? mrowA[col]     : -1e30f;
                    macc[nn][1] = (col + 1 < LLEN) ? mrowA[col + 1] : -1e30f;
                    macc[nn][2] = (col     < LLEN) ? mrowB[col]     : -1e30f;
                    macc[nn][3] = (col + 1 < LLEN) ? mrowB[col + 1] : -1e30f;
                }
            }

            // ---- S = Q K^T ----
            float sacc[8][4];
#pragma unroll
            for (int nn = 0; nn < 8; nn++) {
                sacc[nn][0] = 0.f; sacc[nn][1] = 0.f;
                sacc[nn][2] = 0.f; sacc[nn][3] = 0.f;
#pragma unroll
                for (int kk = 0; kk < 2; kk++) {
                    uint32_t b0, b1, b2, b3;
                    int c_row = kk * 32 + ((lane >> 3) << 3) + (lane & 7);
                    ldsm_x4_t(b0, b1, b2, b3, smem_u32(Kt + c_row * KS_STRIDE + nn * 8));
                    mma16816(sacc[nn], qf[2*kk][0],   qf[2*kk][1],   qf[2*kk][2],   qf[2*kk][3],   b0, b1);
                    mma16816(sacc[nn], qf[2*kk+1][0], qf[2*kk+1][1], qf[2*kk+1][2], qf[2*kk+1][3], b2, b3);
                }
                sacc[nn][0] += macc[nn][0];
                sacc[nn][1] += macc[nn][1];
                sacc[nn][2] += macc[nn][2];
                sacc[nn][3] += macc[nn][3];
            }

            // ---- online softmax (rows g, g+8) ----
            float rmax0 = -1e30f, rmax1 = -1e30f;
#pragma unroll
            for (int nn = 0; nn < 8; nn++) {
                rmax0 = fmaxf(rmax0, fmaxf(sacc[nn][0], sacc[nn][1]));
                rmax1 = fmaxf(rmax1, fmaxf(sacc[nn][2], sacc[nn][3]));
            }
            rmax0 = fmaxf(rmax0, __shfl_xor_sync(0xffffffffu, rmax0, 1));
            rmax0 = fmaxf(rmax0, __shfl_xor_sync(0xffffffffu, rmax0, 2));
            rmax1 = fmaxf(rmax1, __shfl_xor_sync(0xffffffffu, rmax1, 1));
            rmax1 = fmaxf(rmax1, __shfl_xor_sync(0xffffffffu, rmax1, 2));

            float mn0 = fmaxf(m0, rmax0), mn1 = fmaxf(m1, rmax1);
            float al0 = __expf(m0 - mn0), al1 = __expf(m1 - mn1);
            float rs0 = 0.f, rs1 = 0.f;
#pragma unroll
            for (int nn = 0; nn < 8; nn++) {
                sacc[nn][0] = __expf(sacc[nn][0] - mn0);
                sacc[nn][1] = __expf(sacc[nn][1] - mn0);
                sacc[nn][2] = __expf(sacc[nn][2] - mn1);
                sacc[nn][3] = __expf(sacc[nn][3] - mn1);
                rs0 += sacc[nn][0] + sacc[nn][1];
                rs1 += sacc[nn][2] + sacc[nn][3];
            }
            rs0 += __shfl_xor_sync(0xffffffffu, rs0, 1);
            rs0 += __shfl_xor_sync(0xffffffffu, rs0, 2);
            rs1 += __shfl_xor_sync(0xffffffffu, rs1, 1);
            rs1 += __shfl_xor_sync(0xffffffffu, rs1, 2);
            l0 = l0 * al0 + rs0;  m0 = mn0;
            l1 = l1 * al1 + rs1;  m1 = mn1;

#pragma unroll
            for (int nn = 0; nn < 8; nn++) {
                oacc[nn][0] *= al0; oacc[nn][1] *= al0;
                oacc[nn][2] *= al1; oacc[nn][3] *= al1;
            }

            // ---- P fragments ----
            uint32_t pf[4][4];
#pragma unroll
            for (int kp = 0; kp < 4; kp++) {
                pf[kp][0] = pack_h2(sacc[2*kp][0],   sacc[2*kp][1]);
                pf[kp][1] = pack_h2(sacc[2*kp][2],   sacc[2*kp][3]);
                pf[kp][2] = pack_h2(sacc[2*kp+1][0], sacc[2*kp+1][1]);
                pf[kp][3] = pack_h2(sacc[2*kp+1][2], sacc[2*kp+1][3]);
            }

            // ---- O += P V^T ----
#pragma unroll
            for (int np = 0; np < 8; np++) {
#pragma unroll
                for (int kk = 0; kk < 2; kk++) {
                    uint32_t b0, b1, b2, b3;
                    int c_row = np * 8 + (lane & 7);
                    int s_col = kk * 32 + ((lane >> 3) << 3);
                    ldsm_x4(b0, b1, b2, b3, smem_u32(Vt + c_row * KS_STRIDE + s_col));
                    mma16816(oacc[np], pf[2*kk][0],   pf[2*kk][1],   pf[2*kk][2],   pf[2*kk][3],   b0, b1);
                    mma16816(oacc[np], pf[2*kk+1][0], pf[2*kk+1][1], pf[2*kk+1][2], pf[2*kk+1][3], b2, b3);
                }
            }
        }
    }

    // ---- epilogue ----
    __syncthreads();
    float inv0 = 1.f / l0, inv1 = 1.f / l1;
#pragma unroll
    for (int np = 0; np < 8; np++) {
        int c = np * 8 + tg * 2;
        Os[(tw + g)     * OS_STRIDE + c]     = oacc[np][0] * inv0;
        Os[(tw + g)     * OS_STRIDE + c + 1] = oacc[np][1] * inv0;
        Os[(tw + g + 8) * OS_STRIDE + c]     = oacc[np][2] * inv1;
        Os[(tw + g + 8) * OS_STRIDE + c + 1] = oacc[np][3] * inv1;
    }
    __syncthreads();

    float* ob = out + (size_t)n * CHD * TLEN + t0;
    for (int idx = tid; idx < CHD * BT; idx += 256) {
        int c = idx >> 7, t = idx & 127;
        ob[c * TLEN + t] = Os[t * OS_STRIDE + c];
    }
}

extern "C" void kernel_launch(void* const* d_in, const int* in_sizes, int n_in,
                              void* d_out, int out_size)
{
    const float* qkv  = (const float*)d_in[0];   // [32, 192, 2048]
    const float* enc  = (const float*)d_in[1];   // [32, 128, 77]
    const float* mask = (const float*)d_in[2];   // [1, 2048, 2125]
    float* out = (float*)d_out;                  // [32, 64, 2048]

    int nconv = NB * CHD * SP;
    convert_kv_kernel<<<(nconv + 255) / 256, 256>>>(qkv, enc);

    cudaFuncSetAttribute(attn_fa16_kernel,
                         cudaFuncAttributeMaxDynamicSharedMemorySize, SMEM_TOTAL);
    dim3 grid(TLEN / BT, NB);   // (16, 32)
    attn_fa16_kernel<<<grid, 256, SMEM_TOTAL>>>(qkv, mask, out);
}